// round 6
// baseline (speedup 1.0000x reference)
#include <cuda_runtime.h>
#include <cstdint>
#include <cstdio>

// GRU over T2=256 steps; rows (B*T1 = 4096) fully independent.
// 128 persistent CTAs x 256 threads, 32 rows per CTA, weights in SMEM,
// fp32 math via packed fma.rn.f32x2 (Blackwell packed-f32 pipe).

#define T2V 256
#define DV  64
#define RR  32          // rows per CTA
#define NCTA 128
#define NT  256
#define GS  34          // padded row stride (floats) for transposed state slabs

// SMEM float offsets
#define OFF_WP1 0                       // 128*128 : [k][o], o<64 -> Wr col o, o>=64 -> Wz col o-64
#define OFF_WH  (128*128)               // 128*64  : Wh[k][c]
#define OFF_G   (OFF_WH + 128*64)       // 128*GS  : g[k][row]; k<64 = xt^T, k>=64 = h^T (then h*r^T)
#define OFF_HB  (OFF_G  + 128*GS)       // 64*GS   : h[c][row]
#define OFF_ZB  (OFF_HB + 64*GS)        // 64*GS   : z[c][row]
#define SMEM_FLOATS (OFF_ZB + 64*GS)
#define SMEM_BYTES  (SMEM_FLOATS * 4)

__device__ __forceinline__ unsigned long long pk2(float lo, float hi) {
    unsigned long long r;
    asm("mov.b64 %0, {%1, %2};" : "=l"(r) : "f"(lo), "f"(hi));
    return r;
}
__device__ __forceinline__ float2 upk2(unsigned long long v) {
    float2 f;
    asm("mov.b64 {%0, %1}, %2;" : "=f"(f.x), "=f"(f.y) : "l"(v));
    return f;
}
__device__ __forceinline__ void ffma2(unsigned long long& d, unsigned long long a,
                                      unsigned long long b) {
    asm("fma.rn.f32x2 %0, %1, %2, %0;" : "+l"(d) : "l"(a), "l"(b));
}
// sigmoid via ex2.approx + rcp.approx : ~1e-6 abs err
__device__ __forceinline__ float fsig(float x) {
    float e;
    asm("ex2.approx.f32 %0, %1;" : "=f"(e) : "f"(x * -1.4426950408889634f));
    float r;
    asm("rcp.approx.f32 %0, %1;" : "=f"(r) : "f"(1.0f + e));
    return r;
}
__device__ __forceinline__ float ftanh_(float x) {
    return fmaf(2.0f, fsig(2.0f * x), -1.0f);
}

__global__ void __launch_bounds__(NT, 1)
gru4d_kernel(const float* __restrict__ x,
             const float* __restrict__ kh,
             const float* __restrict__ kr,
             const float* __restrict__ kz,
             const float* __restrict__ bh,
             const float* __restrict__ br,
             const float* __restrict__ bz,
             float* __restrict__ out) {
    extern __shared__ float sm[];
    float* sWp1 = sm + OFF_WP1;
    float* sWh  = sm + OFF_WH;
    float* sg   = sm + OFF_G;
    float* shb  = sm + OFF_HB;
    float* szb  = sm + OFF_ZB;

    const int tid  = threadIdx.x;
    const int c    = tid & 63;   // column lane (phase1: output pair 2c,2c+1 of 128; phase2: col c)
    const int rs   = tid >> 6;   // row slot: rows rs*8 .. rs*8+7
    const int row0 = blockIdx.x * RR;
    const size_t rstride = (size_t)T2V * DV;

    // ---- stage weights into SMEM (Wr|Wz packed over output dim) ----
    for (int idx = tid; idx < 128 * 128; idx += NT) {
        int k = idx >> 7, o = idx & 127;
        sWp1[idx] = (o < 64) ? kr[k * 64 + o] : kz[k * 64 + (o - 64)];
    }
    for (int idx = tid; idx < 128 * 64; idx += NT) sWh[idx] = kh[idx];

    // ---- biases for this lane's output columns ----
    float b0, b1;
    if (c < 32) { b0 = br[2 * c];        b1 = br[2 * c + 1]; }
    else        { b0 = bz[2 * (c - 32)]; b1 = bz[2 * (c - 32) + 1]; }
    const float bhq = bh[c];

    // ---- init: h0 = x[:,:,0,:]; stage x[:,:,1,:] as xt for step t=1 ----
    {
        const float* xp0 = x + (size_t)(row0 + rs * 8) * rstride + c;
        #pragma unroll
        for (int i = 0; i < 8; i++) {
            int row = rs * 8 + i;
            float h0v = xp0[(size_t)i * rstride];           // t = 0
            float x1v = xp0[(size_t)i * rstride + DV];      // t = 1
            shb[c * GS + row]       = h0v;
            sg[(64 + c) * GS + row] = h0v;
            sg[c * GS + row]        = x1v;
        }
    }
    __syncthreads();

    const float2* wp = (const float2*)&sWp1[2 * c];

    for (int t = 1; t < T2V; ++t) {
        // ---- prefetch x_{t+1} (global, hidden under phase-1 compute) ----
        float xv[8];
        if (t < T2V - 1) {
            const float* xp = x + (size_t)(row0 + rs * 8) * rstride
                                + (size_t)(t + 1) * DV + c;
            #pragma unroll
            for (int i = 0; i < 8; i++) xv[i] = xp[(size_t)i * rstride];
        }

        // ========== phase 1: r|z pre-acts, K=128, 128 output cols ==========
        unsigned long long acc[4][2];
        #pragma unroll
        for (int i = 0; i < 4; i++) { acc[i][0] = pk2(b0, b0); acc[i][1] = pk2(b1, b1); }

        #pragma unroll 4
        for (int k = 0; k < 128; k++) {
            float2 w = wp[(size_t)k * 64];                 // sWp1[k*128 + 2c .. +1]
            unsigned long long w0 = pk2(w.x, w.x);
            unsigned long long w1 = pk2(w.y, w.y);
            const double* gp = (const double*)&sg[k * GS + rs * 8];  // warp-broadcast
            #pragma unroll
            for (int i = 0; i < 4; i++) {
                unsigned long long g2 = __double_as_longlong(gp[i]); // rows 2i,2i+1
                ffma2(acc[i][0], g2, w0);
                ffma2(acc[i][1], g2, w1);
            }
        }
        __syncthreads();   // all phase-1 reads of sg done

        // ---- epilogue 1: sigmoid; r-lanes write h*r into sg.h, z-lanes write z ----
        {
            const bool isR  = (c < 32);
            const int cbase = isR ? 2 * c : 2 * (c - 32);
            #pragma unroll
            for (int i = 0; i < 4; i++) {
                int row = rs * 8 + 2 * i;
                #pragma unroll
                for (int j = 0; j < 2; j++) {
                    float2 pa = upk2(acc[i][j]);
                    float s0 = fsig(pa.x);
                    float s1 = fsig(pa.y);
                    int cj = cbase + j;
                    if (isR) {
                        float2 h2 = *(const float2*)&shb[cj * GS + row];
                        *(float2*)&sg[(64 + cj) * GS + row] =
                            make_float2(h2.x * s0, h2.y * s1);
                    } else {
                        *(float2*)&szb[cj * GS + row] = make_float2(s0, s1);
                    }
                }
            }
        }
        __syncthreads();   // g2 = [xt | h*r] and z ready

        // ========== phase 2: h_cand pre-act, K=128, 64 output cols ==========
        unsigned long long a2[4];
        #pragma unroll
        for (int i = 0; i < 4; i++) a2[i] = pk2(bhq, bhq);

        #pragma unroll 4
        for (int k = 0; k < 128; k++) {
            float w = sWh[k * 64 + c];
            unsigned long long wb = pk2(w, w);
            const double* gp = (const double*)&sg[k * GS + rs * 8];
            #pragma unroll
            for (int i = 0; i < 4; i++)
                ffma2(a2[i], __double_as_longlong(gp[i]), wb);
        }
        __syncthreads();   // all phase-2 reads of sg done

        // ---- epilogue 2: tanh + blend; write h into shb & sg.h; stage x_{t+1} ----
        #pragma unroll
        for (int i = 0; i < 4; i++) {
            int row = rs * 8 + 2 * i;
            float2 pa = upk2(a2[i]);
            float hc0 = ftanh_(pa.x);
            float hc1 = ftanh_(pa.y);
            float2 z2 = *(const float2*)&szb[c * GS + row];
            float2 h2 = *(const float2*)&shb[c * GS + row];
            float hn0 = fmaf(z2.x, hc0 - h2.x, h2.x);   // (1-z)h + z*hc
            float hn1 = fmaf(z2.y, hc1 - h2.y, h2.y);
            *(float2*)&shb[c * GS + row]       = make_float2(hn0, hn1);
            *(float2*)&sg[(64 + c) * GS + row] = make_float2(hn0, hn1);
        }
        if (t < T2V - 1) {
            #pragma unroll
            for (int i = 0; i < 8; i++)
                sg[c * GS + rs * 8 + i] = xv[i];
        }
        __syncthreads();   // state published for next step
    }

    // ---- write h_final: out[row][c], coalesced per warp ----
    #pragma unroll
    for (int i = 0; i < 8; i++) {
        int row = rs * 8 + i;
        out[(size_t)(row0 + row) * DV + c] = shb[c * GS + row];
    }
}

extern "C" void kernel_launch(void* const* d_in, const int* in_sizes, int n_in,
                              void* d_out, int out_size) {
    const float* x  = (const float*)d_in[0];
    const float* kh = (const float*)d_in[1];
    const float* kr = (const float*)d_in[2];
    const float* kz = (const float*)d_in[3];
    const float* bh = (const float*)d_in[4];
    const float* br = (const float*)d_in[5];
    const float* bz = (const float*)d_in[6];
    float* out = (float*)d_out;

    static bool attr_set = false;
    if (!attr_set) {
        cudaFuncSetAttribute(gru4d_kernel,
                             cudaFuncAttributeMaxDynamicSharedMemorySize,
                             SMEM_BYTES);
        attr_set = true;
    }
    gru4d_kernel<<<NCTA, NT, SMEM_BYTES>>>(x, kh, kr, kz, bh, br, bz, out);
}